// round 10
// baseline (speedup 1.0000x reference)
#include <cuda_runtime.h>
#include <cuda_bf16.h>
#include <cstdint>

#define S 4096
#define GRID 128
#define BLOCK 512
#define NWARP 16
#define RPB 32             // rows per block
#define RPG 8              // rows per warp
#define KQ 1024            // K quarter per warp
#define ROWSTRIDE (S / 8)  // uint4 per row

// ---------------- device-global scratch ----------------
static __device__ __nv_bfloat16 g_M[(size_t)S * S];     // exp(log_trans), bf16
static __device__ float g_w[2][S];                      // ping-pong unnormalized filter
static __device__ unsigned long long g_flag[2][GRID];   // {f32 partialZ:hi, u32 gen:lo}

// ---------------- prep: M = bf16(exp(log_trans)); reset flags ----------------
__global__ void hmm_prep_kernel(const float* __restrict__ log_trans) {
    size_t gtid = (size_t)blockIdx.x * blockDim.x + threadIdx.x;
    if (gtid < 2 * GRID) g_flag[gtid / GRID][gtid % GRID] = 0ull;
    const size_t n4 = (size_t)S * S / 4;
    const size_t stride = (size_t)gridDim.x * blockDim.x;
    for (size_t i = gtid; i < n4; i += stride) {
        float4 v = reinterpret_cast<const float4*>(log_trans)[i];
        __nv_bfloat162 lo, hi;
        lo.x = __float2bfloat16(__expf(v.x));
        lo.y = __float2bfloat16(__expf(v.y));
        hi.x = __float2bfloat16(__expf(v.z));
        hi.y = __float2bfloat16(__expf(v.w));
        reinterpret_cast<__nv_bfloat162*>(g_M)[2 * i]     = lo;
        reinterpret_cast<__nv_bfloat162*>(g_M)[2 * i + 1] = hi;
    }
}

// ---------------- helpers ----------------
__device__ __forceinline__ float warp_sum(float v) {
#pragma unroll
    for (int o = 16; o; o >>= 1) v += __shfl_xor_sync(0xffffffffu, v, o);
    return v;
}

// EXACT bf16 pair -> f32x2
__device__ __forceinline__ unsigned long long cvt2(unsigned u) {
    unsigned long long r;
    asm("mov.b64 %0, {%1, %2};" : "=l"(r) : "r"(u << 16), "r"(u & 0xffff0000u));
    return r;
}

__device__ __forceinline__ unsigned long long fma2(unsigned long long a,
                                                   unsigned long long b,
                                                   unsigned long long c) {
    unsigned long long d;
    asm("fma.rn.f32x2 %0, %1, %2, %3;" : "=l"(d) : "l"(a), "l"(b), "l"(c));
    return d;
}

__device__ __forceinline__ float f32x2_hsum(unsigned long long v) {
    unsigned lo, hi;
    asm("mov.b64 {%0, %1}, %2;" : "=r"(lo), "=r"(hi) : "l"(v));
    return __uint_as_float(lo) + __uint_as_float(hi);
}

__device__ __forceinline__ unsigned long long ldacq(const unsigned long long* p) {
    unsigned long long v;
    asm volatile("ld.acquire.gpu.global.b64 %0, [%1];" : "=l"(v) : "l"(p) : "memory");
    return v;
}
__device__ __forceinline__ void strel(unsigned long long* p, unsigned long long v) {
    asm volatile("st.release.gpu.global.b64 [%0], %1;" :: "l"(p), "l"(v) : "memory");
}
__device__ __forceinline__ void strelax(float* p, float v) {
    asm volatile("st.relaxed.gpu.global.f32 [%0], %1;" :: "l"(p), "f"(v) : "memory");
}
__device__ __forceinline__ uint4 ldcg4(const uint4* p) {
    float4 t = __ldcg(reinterpret_cast<const float4*>(p));
    return *reinterpret_cast<uint4*>(&t);
}

// Barrier + Z-reduce (warp-collective). Ping-pong slots keep exact-match
// spin deadlock-free: slot of gen is rewritten only at gen+2, which requires
// every block to have exited poll(gen).
__device__ __forceinline__ float poll_all(unsigned gen, int lane) {
    const unsigned long long* base = g_flag[gen & 1];
    unsigned long long x0, x1, x2, x3;
    for (;;) {
        x0 = ldacq(base + lane);
        x1 = ldacq(base + lane + 32);
        x2 = ldacq(base + lane + 64);
        x3 = ldacq(base + lane + 96);
        if (((unsigned)x0 == gen) & ((unsigned)x1 == gen) &
            ((unsigned)x2 == gen) & ((unsigned)x3 == gen)) break;
    }
    float z = __uint_as_float((unsigned)(x0 >> 32)) +
              __uint_as_float((unsigned)(x1 >> 32)) +
              __uint_as_float((unsigned)(x2 >> 32)) +
              __uint_as_float((unsigned)(x3 >> 32));
    return warp_sum(z);
}

// ---------------- persistent forward-filter kernel ----------------
__global__ void __launch_bounds__(BLOCK, 1) hmm_main_kernel(
    const float* __restrict__ log_M0,
    const float* __restrict__ log_emit,
    const int*   __restrict__ Tptr,
    float*       __restrict__ out)
{
    __shared__ float sw[S];                       // staged w (linear space)
    __shared__ __align__(16) float s_red[RPB][4];
    __shared__ float s_Z[2];                      // poll results (by gen parity)

    const int tid  = threadIdx.x;
    const int lane = tid & 31;
    const int warp = tid >> 5;
    const int g    = warp >> 2;   // row group 0..3
    const int q    = warp & 3;    // K quarter 0..3
    const int bid  = blockIdx.x;
    const int T    = *Tptr;

    const int r0 = bid * RPB;
    const uint4* A = reinterpret_cast<const uint4*>(
        g_M + (size_t)(r0 + g * RPG) * S + q * KQ);
    const float* swq = sw + q * KQ;

    double lik = 0.0;   // lives in warp 1 (the poll warp)

    // ---- t = 0: warp 0 builds+publishes w0; warp 1 polls gen 1 ----
    if (warp == 0) {
        int row = r0 + lane;
        float v = __expf(__ldcg(log_M0 + row) + __ldcg(log_emit + row));
        strelax(&g_w[0][row], v);
        float part = warp_sum(v);
        __syncwarp();
        if (lane == 0)
            strel(&g_flag[1][bid],
                  ((unsigned long long)__float_as_uint(part) << 32) | 1u);
    }
    if (warp == 1) {
        float Z = poll_all(1u, lane);            // gen 1 -> slot 1 -> s_Z[1]
        if (lane == 0) {
            s_Z[1] = Z;
            if (bid == 0) lik += (double)logf(Z);
        }
    }
    __syncthreads();   // broadcast: w0 visible + s_Z[1] set

    for (int t = 1; t <= T; ++t) {
        const int cur = t & 1, prev = cur ^ 1;
        const unsigned gen = (unsigned)(t + 1);

        // prefetch first streamed chunk (rows 6,7, c=0); rest double-buffered
        uint4 p6 = ldcg4(A + 6 * ROWSTRIDE + lane);
        uint4 p7 = ldcg4(A + 7 * ROWSTRIDE + lane);

        // emit prefetch (warp 0 only; consumed in epilogue)
        float em = 0.f;
        if (warp == 0) em = __ldcg(log_emit + (size_t)t * S + r0 + lane);

        // broadcast w_{t-1} into smem (each warp copies its 1/16 slice)
        {
            int j = warp * 64 + lane;
            float4 a = __ldcg(reinterpret_cast<const float4*>(g_w[prev]) + j);
            reinterpret_cast<float4*>(sw)[j] = a;
            j += 32;
            float4 b = __ldcg(reinterpret_cast<const float4*>(g_w[prev]) + j);
            reinterpret_cast<float4*>(sw)[j] = b;
        }
        __syncthreads();

        // --- dot: rows 0..5 L1-pinned, rows 6..7 streamed (double-buffered) ---
        unsigned long long acc[8] = {0ull, 0ull, 0ull, 0ull, 0ull, 0ull, 0ull, 0ull};
#pragma unroll
        for (int c = 0; c < 4; ++c) {
            const int kb = c * 32 + lane;
            uint4 n6, n7;
            if (c < 3) {   // prefetch next streamed chunk
                n6 = ldcg4(A + 6 * ROWSTRIDE + kb + 32);
                n7 = ldcg4(A + 7 * ROWSTRIDE + kb + 32);
            }
            const ulonglong2 w01 = *reinterpret_cast<const ulonglong2*>(swq + c * 256 + lane * 8);
            const ulonglong2 w23 = *reinterpret_cast<const ulonglong2*>(swq + c * 256 + lane * 8 + 4);
#pragma unroll
            for (int r = 0; r < 6; ++r) {
                uint4 a = A[r * ROWSTRIDE + kb];
                acc[r] = fma2(cvt2(a.x), w01.x, acc[r]);
                acc[r] = fma2(cvt2(a.y), w01.y, acc[r]);
                acc[r] = fma2(cvt2(a.z), w23.x, acc[r]);
                acc[r] = fma2(cvt2(a.w), w23.y, acc[r]);
            }
            acc[6] = fma2(cvt2(p6.x), w01.x, acc[6]);
            acc[6] = fma2(cvt2(p6.y), w01.y, acc[6]);
            acc[6] = fma2(cvt2(p6.z), w23.x, acc[6]);
            acc[6] = fma2(cvt2(p6.w), w23.y, acc[6]);
            acc[7] = fma2(cvt2(p7.x), w01.x, acc[7]);
            acc[7] = fma2(cvt2(p7.y), w01.y, acc[7]);
            acc[7] = fma2(cvt2(p7.z), w23.x, acc[7]);
            acc[7] = fma2(cvt2(p7.w), w23.y, acc[7]);
            p6 = n6; p7 = n7;
        }

#pragma unroll
        for (int r = 0; r < 8; ++r) {
            float s = warp_sum(f32x2_hsum(acc[r]));
            if (lane == 0) s_red[g * RPG + r][q] = s;
        }
        __syncthreads();

        // epilogue (warp 0) OVERLAPPED with poll (warp 1)
        if (warp == 0) {
            float4 p = *reinterpret_cast<const float4*>(s_red[lane]);
            float dotv = (p.x + p.y) + (p.z + p.w);
            float invZ = 1.0f / s_Z[t & 1];          // Z_{t-1}, set last step
            float v = dotv * __expf(em) * invZ;
            strelax(&g_w[cur][r0 + lane], v);
            float part = warp_sum(v);
            __syncwarp();
            if (lane == 0)
                strel(&g_flag[gen & 1][bid],
                      ((unsigned long long)__float_as_uint(part) << 32) | gen);
        } else if (warp == 1) {
            float Z = poll_all(gen, lane);           // detection overlaps epilogue
            if (lane == 0) {
                s_Z[gen & 1] = Z;
                if (bid == 0) lik += (double)logf(Z);
            }
        }
        __syncthreads();   // broadcast acquire: w_t visible to whole block
    }

    if (bid == 0 && warp == 1 && lane == 0) out[0] = (float)lik;
}

// ---------------- launch ----------------
extern "C" void kernel_launch(void* const* d_in, const int* in_sizes, int n_in,
                              void* d_out, int out_size) {
    const float* log_M0    = (const float*)d_in[0];
    const float* log_trans = (const float*)d_in[1];
    const float* log_emit  = (const float*)d_in[2];
    const int*   Tptr      = (const int*)d_in[3];
    float* out = (float*)d_out;

    // minimize smem carveout -> maximize L1D so the 192KB pinned M rows fit
    cudaFuncSetAttribute(hmm_main_kernel,
                         cudaFuncAttributePreferredSharedMemoryCarveout, 8);

    hmm_prep_kernel<<<2048, 256>>>(log_trans);
    hmm_main_kernel<<<GRID, BLOCK>>>(log_M0, log_emit, Tptr, out);
}